// round 14
// baseline (speedup 1.0000x reference)
#include <cuda_runtime.h>
#include <math_constants.h>

// VectorQuantizer: B=32, D=64, H=W=32, K=1024
// Output layout (f32 concat): [loss(1)][quantized BxDxHxW (2097152)][indices BxHW (32768)]

#define ND 64
#define NHW 1024
#define NK 1024
#define NPTS 32768
#define CHUNK 8
#define CODES_PER_CHUNK (NK / CHUNK)              // 128
#define CODES_PER_ITER 16
#define NITER (CODES_PER_CHUNK / CODES_PER_ITER)  // 8
#define SCAN_THREADS 128
#define SCAN_BLOCKS (CHUNK * NPTS / SCAN_THREADS) // 2048
#define NGROUPS (NPTS / SCAN_THREADS)             // 256

__device__ float              g_e2[NK];
__device__ unsigned long long g_best[NPTS];       // (dist_bits<<32)|code
__device__ double             g_partials[NGROUPS];
__device__ int                g_done[NGROUPS];    // per-group finished-chunk count
__device__ int                g_lossfin;          // finished-group count

// ---------------------------------------------------------------------------
// Packed f32x2 helpers (sm_103a; ptxas never auto-fuses these)
// ---------------------------------------------------------------------------
__device__ __forceinline__ unsigned long long pack2(float a, float b) {
    unsigned long long r;
    asm("mov.b64 %0, {%1, %2};" : "=l"(r) : "f"(a), "f"(b));
    return r;
}
__device__ __forceinline__ float2 unpack2(unsigned long long v) {
    float2 f;
    asm("mov.b64 {%0, %1}, %2;" : "=f"(f.x), "=f"(f.y) : "l"(v));
    return f;
}
__device__ __forceinline__ unsigned long long fma2(unsigned long long a,
                                                   unsigned long long b,
                                                   unsigned long long c) {
    unsigned long long d;
    asm("fma.rn.f32x2 %0, %1, %2, %3;" : "=l"(d) : "l"(a), "l"(b), "l"(c));
    return d;
}
__device__ __forceinline__ unsigned long long mul2(unsigned long long a,
                                                   unsigned long long b) {
    unsigned long long d;   // fl(a*b) == fl(a*b+0): bit-identical to fma2 with 0
    asm("mul.rn.f32x2 %0, %1, %2;" : "=l"(d) : "l"(a), "l"(b));
    return d;
}

// ---------------------------------------------------------------------------
// Prep: e2 (proven order) + init g_best/counters (re-run every graph replay)
// ---------------------------------------------------------------------------
__global__ void vq_prep_kernel(const float* __restrict__ emb) {
    int tid = blockIdx.x * 256 + threadIdx.x;   // 8192 threads
    int k   = tid >> 3;
    int sub = tid & 7;
    const float* r = emb + k * ND + sub * 8;
    float s = 0.f;
#pragma unroll
    for (int d = 0; d < 8; d++) s = __fmaf_rn(r[d], r[d], s);
    s += __shfl_down_sync(0xffffffffu, s, 4, 8);
    s += __shfl_down_sync(0xffffffffu, s, 2, 8);
    s += __shfl_down_sync(0xffffffffu, s, 1, 8);
    if (sub == 0) g_e2[k] = s;
#pragma unroll
    for (int i = 0; i < 4; i++)
        g_best[tid + 8192 * i] = 0xFFFFFFFFFFFFFFFFull;
    if (tid < NGROUPS) g_done[tid] = 0;
    if (tid == NGROUPS) g_lossfin = 0;
}

// ---------------------------------------------------------------------------
// Scan kernel (+fused combine/loss tail): 2048 CTAs x 128 threads.
// blockIdx = point-group(256) x chunk(8); 1 point/thread, 128 codes/CTA.
// Core per-code dot/dist/tie-break sequence is bit-identical to R13 (passing).
// The LAST finishing chunk-CTA of each group performs the combine epilogue
// (gather quantized, index, loss partial) using its register-resident x;
// the last finishing group reduces the loss. Exact u64 atomicMin merge
// (dist > 0 -> float bits monotone; min is order-independent).
// ---------------------------------------------------------------------------
__global__ void __launch_bounds__(SCAN_THREADS, 4) vq_scan_kernel(
    const float* __restrict__ x_in,
    const float* __restrict__ emb,
    float* __restrict__ out)
{
    const int t  = threadIdx.x;
    const int c  = blockIdx.x & (CHUNK - 1);      // chunk id 0..7
    const int g  = blockIdx.x >> 3;               // point group 0..255
    const int n  = g * SCAN_THREADS + t;          // point id
    const int b  = n >> 10;
    const int hw = n & 1023;

    const float* xp = x_in + (size_t)b * (ND * NHW) + hw;

    // Load + pack x (coalesced across lanes); x2 in ascending d (as before).
    unsigned long long xq[32];
    float x2 = 0.f;
#pragma unroll
    for (int p = 0; p < 32; p++) {
        float a  = xp[(2 * p) * NHW];
        float cc = xp[(2 * p + 1) * NHW];
        x2 = __fmaf_rn(a, a, x2);
        x2 = __fmaf_rn(cc, cc, x2);
        xq[p] = pack2(a, cc);
    }

    // Tiles: 16 codes * 64 floats = 256 float4 = 4KB, ping-pong
    __shared__ float4 sbuf[2][CODES_PER_ITER * 16];
    __shared__ double sd[SCAN_THREADS];
    __shared__ int    rank_sh, lrank_sh;
    const float4* __restrict__ embc =
        (const float4*)emb + (size_t)c * CODES_PER_CHUNK * 16;

    sbuf[0][t]       = embc[t];
    sbuf[0][t + 128] = embc[t + 128];
    __syncthreads();

    float bestv = CUDART_INF_F;
    int   besti = 0;
    const int code_base = c * CODES_PER_CHUNK;

#pragma unroll 1
    for (int i = 0; i < NITER; i++) {
        const int cur = i & 1;
        if (i + 1 < NITER) {
            sbuf[cur ^ 1][t]       = embc[(i + 1) * 256 + t];
            sbuf[cur ^ 1][t + 128] = embc[(i + 1) * 256 + 128 + t];
        }

        const ulonglong2* __restrict__ sp = (const ulonglong2*)sbuf[cur];

        unsigned long long acc[CODES_PER_ITER];
#pragma unroll
        for (int j = 0; j < CODES_PER_ITER; j++) {
            // first dim-pair: mul2 == fma2-with-zero (bit-identical init)
            ulonglong2 e0 = sp[j * 16];
            acc[j] = mul2(xq[0], e0.x);
            acc[j] = fma2(xq[1], e0.y, acc[j]);
#pragma unroll
            for (int p2 = 1; p2 < 16; p2++) {
                ulonglong2 e = sp[j * 16 + p2];            // 16B broadcast LDS
                acc[j] = fma2(xq[2 * p2 + 0], e.x, acc[j]);
                acc[j] = fma2(xq[2 * p2 + 1], e.y, acc[j]);
            }
        }

        const int c0 = code_base + i * CODES_PER_ITER;
#pragma unroll
        for (int j = 0; j < CODES_PER_ITER; j++) {
            float e2v = g_e2[c0 + j];
            float2 a  = unpack2(acc[j]);
            float dot = __fadd_rn(a.x, a.y);
            float dv  = __fadd_rn(__fmaf_rn(-2.0f, dot, x2), e2v);
            if (dv < bestv) { bestv = dv; besti = c0 + j; }   // first-index ties
        }
        __syncthreads();
    }

    // dist > 0 (||x-e||^2 scale ~64) -> float bits monotone; exact merge.
    unsigned long long packed =
        ((unsigned long long)__float_as_uint(bestv) << 32) | (unsigned)besti;
    atomicMin(&g_best[n], packed);

    __threadfence();                        // my atomicMin visible before count
    if (t == 0) rank_sh = atomicAdd(&g_done[g], 1);
    __syncthreads();
    if (rank_sh != CHUNK - 1) return;       // not the last chunk for this group

    // ---- fused combine: all 8 chunks of this group are merged in g_best ----
    const int winner = (int)(__ldcg(&g_best[n]) & 0xffffffffu);
    const float4* er4  = (const float4*)(emb + (size_t)winner * ND);
    float*        qout = out + 1 + (size_t)b * (ND * NHW) + hw;

    double lacc = 0.0;
#pragma unroll
    for (int p = 0; p < 16; p++) {
        float4 v  = __ldg(&er4[p]);          // contiguous codebook row, L2-hot
        float2 x0 = unpack2(xq[2 * p]);      // x from registers (same values)
        float2 x1 = unpack2(xq[2 * p + 1]);
        qout[(4 * p + 0) * NHW] = v.x;       // coalesced across lanes
        qout[(4 * p + 1) * NHW] = v.y;
        qout[(4 * p + 2) * NHW] = v.z;
        qout[(4 * p + 3) * NHW] = v.w;
        float d0 = v.x - x0.x, d1 = v.y - x0.y;
        float d2 = v.z - x1.x, d3 = v.w - x1.y;
        lacc += (double)d0 * d0;             // ascending-d order (deterministic)
        lacc += (double)d1 * d1;
        lacc += (double)d2 * d2;
        lacc += (double)d3 * d3;
    }
    out[1 + (size_t)NPTS * ND + n] = (float)winner;   // exact below 2^24

    sd[t] = lacc;
    __syncthreads();
#pragma unroll
    for (int s = SCAN_THREADS / 2; s > 0; s >>= 1) {
        if (t < s) sd[t] += sd[t + s];
        __syncthreads();
    }
    if (t == 0) {
        g_partials[g] = sd[0];
        __threadfence();
        lrank_sh = atomicAdd(&g_lossfin, 1);
    }
    __syncthreads();
    if (lrank_sh != NGROUPS - 1) return;    // not the last finishing group

    // ---- final deterministic loss: fixed tree over 256 group partials ----
    sd[t] = __ldcg(&g_partials[t]) + __ldcg(&g_partials[t + SCAN_THREADS]);
    __syncthreads();
#pragma unroll
    for (int s = SCAN_THREADS / 2; s > 0; s >>= 1) {
        if (t < s) sd[t] += sd[t + s];
        __syncthreads();
    }
    // loss = q_latent + 0.25 * e_latent = 1.25 * mean((q - x)^2)
    if (t == 0)
        out[0] = (float)(1.25 * sd[0] / (double)((size_t)NPTS * ND));
}

// ---------------------------------------------------------------------------
extern "C" void kernel_launch(void* const* d_in, const int* in_sizes, int n_in,
                              void* d_out, int out_size)
{
    const float* a = (const float*)d_in[0];   // inputs  [32,64,32,32]
    const float* e = (const float*)d_in[1];   // embedding [1024,64]
    if (n_in >= 2 && in_sizes[0] == NK * ND && in_sizes[1] == NPTS * ND) {
        const float* t = a; a = e; e = t;     // defensive order swap
    }
    float* out = (float*)d_out;

    vq_prep_kernel<<<32, 256>>>(e);
    vq_scan_kernel<<<SCAN_BLOCKS, SCAN_THREADS>>>(a, e, out);
    (void)out_size;
}

// round 17
// speedup vs baseline: 1.6098x; 1.6098x over previous
#include <cuda_runtime.h>
#include <math_constants.h>

// VectorQuantizer: B=32, D=64, H=W=32, K=1024
// Output layout (f32 concat): [loss(1)][quantized BxDxHxW (2097152)][indices BxHW (32768)]

#define ND 64
#define NHW 1024
#define NK 1024
#define NPTS 32768
#define CHUNK 8
#define CODES_PER_CHUNK (NK / CHUNK)              // 128
#define CODES_PER_ITER 16
#define NITER (CODES_PER_CHUNK / CODES_PER_ITER)  // 8
#define SCAN_THREADS 128
#define SCAN_BLOCKS (CHUNK * NPTS / SCAN_THREADS) // 2048
#define NGROUPS (NPTS / SCAN_THREADS)             // 256

__device__ float              g_e2[NK];
__device__ unsigned long long g_best[NPTS];       // (dist_bits<<32)|code
__device__ double             g_partials[NGROUPS];
__device__ int                g_done[NGROUPS];    // per-group finished-chunk count
__device__ int                g_lossfin;          // finished-group count

// ---------------------------------------------------------------------------
// Packed f32x2 helpers (sm_103a; ptxas never auto-fuses these)
// ---------------------------------------------------------------------------
__device__ __forceinline__ unsigned long long pack2(float a, float b) {
    unsigned long long r;
    asm("mov.b64 %0, {%1, %2};" : "=l"(r) : "f"(a), "f"(b));
    return r;
}
__device__ __forceinline__ float2 unpack2(unsigned long long v) {
    float2 f;
    asm("mov.b64 {%0, %1}, %2;" : "=f"(f.x), "=f"(f.y) : "l"(v));
    return f;
}
__device__ __forceinline__ unsigned long long fma2(unsigned long long a,
                                                   unsigned long long b,
                                                   unsigned long long c) {
    unsigned long long d;
    asm("fma.rn.f32x2 %0, %1, %2, %3;" : "=l"(d) : "l"(a), "l"(b), "l"(c));
    return d;
}

// ---------------------------------------------------------------------------
// Prep: e2 (proven order) + init g_best/counters (re-run every graph replay)
// ---------------------------------------------------------------------------
__global__ void vq_prep_kernel(const float* __restrict__ emb) {
    int tid = blockIdx.x * 256 + threadIdx.x;   // 8192 threads
    int k   = tid >> 3;
    int sub = tid & 7;
    const float* r = emb + k * ND + sub * 8;
    float s = 0.f;
#pragma unroll
    for (int d = 0; d < 8; d++) s = __fmaf_rn(r[d], r[d], s);
    s += __shfl_down_sync(0xffffffffu, s, 4, 8);
    s += __shfl_down_sync(0xffffffffu, s, 2, 8);
    s += __shfl_down_sync(0xffffffffu, s, 1, 8);
    if (sub == 0) g_e2[k] = s;
#pragma unroll
    for (int i = 0; i < 4; i++)
        g_best[tid + 8192 * i] = 0xFFFFFFFFFFFFFFFFull;
    if (tid < NGROUPS) g_done[tid] = 0;
    if (tid == NGROUPS) g_lossfin = 0;
}

// ---------------------------------------------------------------------------
// Scan kernel (+fused combine/loss tail): 2048 CTAs x 128 threads.
// blockIdx = point-group(256) x chunk(8); 1 point/thread, 128 codes/CTA.
// Hot loop is EXACTLY the R13-passing schedule (acc=0 init, uniform 16-load
// batches). The LAST finishing chunk-CTA of each group runs the combine
// epilogue from its register-resident x; the last finishing group reduces
// the loss. Exact u64 atomicMin merge (dist > 0 -> float bits monotone).
// ---------------------------------------------------------------------------
__global__ void __launch_bounds__(SCAN_THREADS, 4) vq_scan_kernel(
    const float* __restrict__ x_in,
    const float* __restrict__ emb,
    float* __restrict__ out)
{
    const int t  = threadIdx.x;
    const int c  = blockIdx.x & (CHUNK - 1);      // chunk id 0..7
    const int g  = blockIdx.x >> 3;               // point group 0..255
    const int n  = g * SCAN_THREADS + t;          // point id
    const int b  = n >> 10;
    const int hw = n & 1023;

    const float* xp = x_in + (size_t)b * (ND * NHW) + hw;

    // Load + pack x (coalesced across lanes); x2 in ascending d (as before).
    unsigned long long xq[32];
    float x2 = 0.f;
#pragma unroll
    for (int p = 0; p < 32; p++) {
        float a  = xp[(2 * p) * NHW];
        float cc = xp[(2 * p + 1) * NHW];
        x2 = __fmaf_rn(a, a, x2);
        x2 = __fmaf_rn(cc, cc, x2);
        xq[p] = pack2(a, cc);
    }

    // Tiles: 16 codes * 64 floats = 256 float4 = 4KB, ping-pong
    __shared__ float4 sbuf[2][CODES_PER_ITER * 16];
    __shared__ double sd[SCAN_THREADS];
    __shared__ int    rank_sh, lrank_sh;
    const float4* __restrict__ embc =
        (const float4*)emb + (size_t)c * CODES_PER_CHUNK * 16;

    sbuf[0][t]       = embc[t];
    sbuf[0][t + 128] = embc[t + 128];
    __syncthreads();

    float bestv = CUDART_INF_F;
    int   besti = 0;
    const int code_base = c * CODES_PER_CHUNK;

#pragma unroll 1
    for (int i = 0; i < NITER; i++) {
        const int cur = i & 1;
        if (i + 1 < NITER) {
            sbuf[cur ^ 1][t]       = embc[(i + 1) * 256 + t];
            sbuf[cur ^ 1][t + 128] = embc[(i + 1) * 256 + 128 + t];
        }

        const ulonglong2* __restrict__ sp = (const ulonglong2*)sbuf[cur];

        unsigned long long acc[CODES_PER_ITER];
#pragma unroll
        for (int j = 0; j < CODES_PER_ITER; j++) acc[j] = 0ull;

#pragma unroll
        for (int j = 0; j < CODES_PER_ITER; j++) {
#pragma unroll
            for (int p2 = 0; p2 < 16; p2++) {
                ulonglong2 e = sp[j * 16 + p2];            // 16B broadcast LDS
                acc[j] = fma2(xq[2 * p2 + 0], e.x, acc[j]);
                acc[j] = fma2(xq[2 * p2 + 1], e.y, acc[j]);
            }
        }

        const int c0 = code_base + i * CODES_PER_ITER;
#pragma unroll
        for (int j = 0; j < CODES_PER_ITER; j++) {
            float e2v = g_e2[c0 + j];
            float2 a  = unpack2(acc[j]);
            float dot = __fadd_rn(a.x, a.y);
            float dv  = __fadd_rn(__fmaf_rn(-2.0f, dot, x2), e2v);
            if (dv < bestv) { bestv = dv; besti = c0 + j; }   // first-index ties
        }
        __syncthreads();
    }

    // dist > 0 (||x-e||^2 scale ~64) -> float bits monotone; exact merge.
    unsigned long long packed =
        ((unsigned long long)__float_as_uint(bestv) << 32) | (unsigned)besti;
    atomicMin(&g_best[n], packed);

    __threadfence();                        // publish atomicMin before counting
    if (t == 0) rank_sh = atomicAdd(&g_done[g], 1);
    __syncthreads();
    if (rank_sh != CHUNK - 1) return;       // not the last chunk for this group

    // ---- fused combine: all 8 chunks of this group are merged in g_best ----
    const int winner = (int)(__ldcg(&g_best[n]) & 0xffffffffu);
    const float4* er4  = (const float4*)(emb + (size_t)winner * ND);
    float*        qout = out + 1 + (size_t)b * (ND * NHW) + hw;

    double lacc = 0.0;
#pragma unroll
    for (int p = 0; p < 16; p++) {
        float4 v  = __ldg(&er4[p]);          // contiguous codebook row, L2-hot
        float2 x0 = unpack2(xq[2 * p]);      // x from registers (same values)
        float2 x1 = unpack2(xq[2 * p + 1]);
        qout[(4 * p + 0) * NHW] = v.x;       // coalesced across lanes
        qout[(4 * p + 1) * NHW] = v.y;
        qout[(4 * p + 2) * NHW] = v.z;
        qout[(4 * p + 3) * NHW] = v.w;
        float d0 = v.x - x0.x, d1 = v.y - x0.y;
        float d2 = v.z - x1.x, d3 = v.w - x1.y;
        lacc += (double)d0 * d0;             // ascending-d order (deterministic)
        lacc += (double)d1 * d1;
        lacc += (double)d2 * d2;
        lacc += (double)d3 * d3;
    }
    out[1 + (size_t)NPTS * ND + n] = (float)winner;   // exact below 2^24

    sd[t] = lacc;
    __syncthreads();
#pragma unroll
    for (int s = SCAN_THREADS / 2; s > 0; s >>= 1) {
        if (t < s) sd[t] += sd[t + s];
        __syncthreads();
    }
    if (t == 0) {
        g_partials[g] = sd[0];
        __threadfence();
        lrank_sh = atomicAdd(&g_lossfin, 1);
    }
    __syncthreads();
    if (lrank_sh != NGROUPS - 1) return;    // not the last finishing group

    // ---- final deterministic loss: fixed tree over 256 group partials ----
    sd[t] = __ldcg(&g_partials[t]) + __ldcg(&g_partials[t + SCAN_THREADS]);
    __syncthreads();
#pragma unroll
    for (int s = SCAN_THREADS / 2; s > 0; s >>= 1) {
        if (t < s) sd[t] += sd[t + s];
        __syncthreads();
    }
    // loss = q_latent + 0.25 * e_latent = 1.25 * mean((q - x)^2)
    if (t == 0)
        out[0] = (float)(1.25 * sd[0] / (double)((size_t)NPTS * ND));
}

// ---------------------------------------------------------------------------
extern "C" void kernel_launch(void* const* d_in, const int* in_sizes, int n_in,
                              void* d_out, int out_size)
{
    const float* a = (const float*)d_in[0];   // inputs  [32,64,32,32]
    const float* e = (const float*)d_in[1];   // embedding [1024,64]
    if (n_in >= 2 && in_sizes[0] == NK * ND && in_sizes[1] == NPTS * ND) {
        const float* t = a; a = e; e = t;     // defensive order swap
    }
    float* out = (float*)d_out;

    vq_prep_kernel<<<32, 256>>>(e);
    vq_scan_kernel<<<SCAN_BLOCKS, SCAN_THREADS>>>(a, e, out);
    (void)out_size;
}